// round 11
// baseline (speedup 1.0000x reference)
#include <cuda_runtime.h>
#include <cuda_bf16.h>
#include <cstdint>

#define BB   2
#define CC   512
#define TT   16
#define HH   32
#define WW   32
#define NH   8
#define CH   64
#define BSEQ (BB*HH*WW)     // 2048
#define ROWS (BSEQ*TT)      // 32768
#define GK   512            // GEMM K (both GEMMs)

__device__ __nv_bfloat16 g_act[(size_t)ROWS * CC];
__device__ __nv_bfloat16 g_qkv[(size_t)ROWS * 3 * CC];
__device__ __nv_bfloat16 g_attb[(size_t)ROWS * CC];
__device__ __nv_bfloat16 g_proj[(size_t)ROWS * CC];
__device__ __nv_bfloat16 g_wq[(size_t)3 * CC * CC];
__device__ __nv_bfloat16 g_wp[(size_t)CC * CC];

// ---------------------------------------------------------------------------
__device__ __forceinline__ uint32_t smem_u32(const void* p) {
    uint32_t a;
    asm("{ .reg .u64 t; cvta.to.shared.u64 t, %1; cvt.u32.u64 %0, t; }" : "=r"(a) : "l"(p));
    return a;
}
#define SWZ(o) ((o) ^ ((((uint32_t)(o)) >> 3) & 0x70))

__device__ __forceinline__ void cpasync16(uint32_t dst, const void* src) {
    asm volatile("cp.async.cg.shared.global [%0], [%1], 16;" :: "r"(dst), "l"(src));
}
__device__ __forceinline__ void ldsm_x4(uint32_t* r, uint32_t addr) {
    asm volatile("ldmatrix.sync.aligned.m8n8.x4.shared.b16 {%0,%1,%2,%3}, [%4];"
                 : "=r"(r[0]), "=r"(r[1]), "=r"(r[2]), "=r"(r[3]) : "r"(addr));
}
__device__ __forceinline__ float f2tf_f(float x) {
    uint32_t y;
    asm("cvt.rna.tf32.f32 %0, %1;" : "=r"(y) : "r"(__float_as_uint(x)));
    return __uint_as_float(y);
}
__device__ __forceinline__ void mma_tf32(float* c, const uint32_t* a, uint32_t b0, uint32_t b1) {
    asm volatile(
        "mma.sync.aligned.m16n8k8.row.col.f32.tf32.tf32.f32 "
        "{%0,%1,%2,%3}, {%4,%5,%6,%7}, {%8,%9}, {%0,%1,%2,%3};"
        : "+f"(c[0]), "+f"(c[1]), "+f"(c[2]), "+f"(c[3])
        : "r"(a[0]), "r"(a[1]), "r"(a[2]), "r"(a[3]), "r"(b0), "r"(b1));
}
__device__ __forceinline__ void mma_bf16(float* c, const uint32_t* a, uint32_t b0, uint32_t b1) {
    asm volatile(
        "mma.sync.aligned.m16n8k16.row.col.f32.bf16.bf16.f32 "
        "{%0,%1,%2,%3}, {%4,%5,%6,%7}, {%8,%9}, {%0,%1,%2,%3};"
        : "+f"(c[0]), "+f"(c[1]), "+f"(c[2]), "+f"(c[3])
        : "r"(a[0]), "r"(a[1]), "r"(a[2]), "r"(a[3]), "r"(b0), "r"(b1));
}

// ---------------------------------------------------------------------------
__global__ __launch_bounds__(256) void wcvt(const float* __restrict__ qkv_w,
                                            const float* __restrict__ proj_w,
                                            __nv_bfloat16* __restrict__ wq,
                                            __nv_bfloat16* __restrict__ wp) {
    int i = blockIdx.x * 256 + threadIdx.x;
    if (i < 3 * CC * CC) wq[i] = __float2bfloat16_rn(qkv_w[i]);
    if (i < CC * CC)     wp[i] = __float2bfloat16_rn(proj_w[i]);
}

// ---------------------------------------------------------------------------
// BF16 tensor GEMM-NT: C[M,N] = A[M,GK] @ W[N,GK]^T + bias, bf16 out
// CTA 128x128, BK=64, 8 warps (64x32 each), 3-stage cp.async, K=512 fixed.
// ---------------------------------------------------------------------------
#define NSTAGE   3
#define STAGE_SZ 32768
#define GSMEM_SZ (NSTAGE*STAGE_SZ)
#define NCH      (GK >> 6)          // 8

__global__ __launch_bounds__(256, 2) void tc_gemm(const __nv_bfloat16* __restrict__ A,
                                                  const __nv_bfloat16* __restrict__ W,
                                                  const float* __restrict__ bias,
                                                  __nv_bfloat16* __restrict__ C,
                                                  int M, int N) {
    extern __shared__ __align__(1024) char smraw[];
    const uint32_t base = smem_u32(smraw);

    const int tid  = threadIdx.x;
    const int wid  = tid >> 5, lane = tid & 31;
    const int wm   = wid & 1, wn = wid >> 1;
    const int bn   = blockIdx.x, bm = blockIdx.y;

    uint32_t st_off[4];
    const __nv_bfloat16* ga[4];
    const __nv_bfloat16* gw[4];
    #pragma unroll
    for (int it = 0; it < 4; it++) {
        int idx = tid + it * 256;
        int r = idx >> 3, c16 = idx & 7;
        st_off[it] = SWZ((uint32_t)(r * 128 + c16 * 16));
        ga[it] = A + (size_t)(bm * 128 + r) * GK + c16 * 8;
        gw[it] = W + (size_t)(bn * 128 + r) * GK + c16 * 8;
    }

    auto load_chunk = [&](int l) {
        const int k0 = l << 6;
        const uint32_t sA = base + (l % NSTAGE) * STAGE_SZ;
        const uint32_t sB = sA + 16384;
        #pragma unroll
        for (int it = 0; it < 4; it++) {
            cpasync16(sA + st_off[it], ga[it] + k0);
            cpasync16(sB + st_off[it], gw[it] + k0);
        }
        asm volatile("cp.async.commit_group;" ::: "memory");
    };

    load_chunk(0);
    load_chunk(1);

    const int m_row_in = ((lane >> 3) & 1) * 8 + (lane & 7);
    const int m_kb     = (lane >> 4) * 16;
    uint32_t a_off[4], b_off[2];
    #pragma unroll
    for (int f = 0; f < 4; f++) {
        int row = wm * 64 + f * 16 + m_row_in;
        a_off[f] = (uint32_t)(row * 128 + (m_kb ^ ((row & 7) << 4)));
    }
    #pragma unroll
    for (int p = 0; p < 2; p++) {
        int row = wn * 32 + p * 16 + m_row_in;
        b_off[p] = (uint32_t)(row * 128 + (m_kb ^ ((row & 7) << 4)));
    }

    float acc[4][4][4];
    #pragma unroll
    for (int f = 0; f < 4; f++)
        #pragma unroll
        for (int g = 0; g < 4; g++)
            #pragma unroll
            for (int r = 0; r < 4; r++) acc[f][g][r] = 0.f;

    #pragma unroll
    for (int c = 0; c < NCH; c++) {
        asm volatile("cp.async.wait_group 1;" ::: "memory");
        __syncthreads();

        if (c + 2 < NCH) load_chunk(c + 2);

        const uint32_t sA = base + (c % NSTAGE) * STAGE_SZ;
        const uint32_t sB = sA + 16384;

        #pragma unroll
        for (int ks = 0; ks < 4; ks++) {
            uint32_t a[4][4], b[2][4];
            #pragma unroll
            for (int f = 0; f < 4; f++)
                ldsm_x4(a[f], sA + (a_off[f] ^ (ks << 5)));
            #pragma unroll
            for (int p = 0; p < 2; p++)
                ldsm_x4(b[p], sB + (b_off[p] ^ (ks << 5)));

            #pragma unroll
            for (int f = 0; f < 4; f++)
                #pragma unroll
                for (int g = 0; g < 4; g++)
                    mma_bf16(acc[f][g], a[f], b[g >> 1][g & 1], b[g >> 1][(g & 1) + 2]);
        }
        __syncthreads();
    }

    const int col_in = 2 * (lane & 3);
    #pragma unroll
    for (int g = 0; g < 4; g++) {
        const int col = bn * 128 + wn * 32 + g * 8 + col_in;
        const float b0 = bias[col], b1 = bias[col + 1];
        #pragma unroll
        for (int f = 0; f < 4; f++) {
            const size_t r0 = (size_t)bm * 128 + wm * 64 + f * 16 + (lane >> 2);
            __nv_bfloat162 p0, p1;
            p0.x = __float2bfloat16_rn(acc[f][g][0] + b0);
            p0.y = __float2bfloat16_rn(acc[f][g][1] + b1);
            p1.x = __float2bfloat16_rn(acc[f][g][2] + b0);
            p1.y = __float2bfloat16_rn(acc[f][g][3] + b1);
            *(__nv_bfloat162*)(C + r0 * N + col)       = p0;
            *(__nv_bfloat162*)(C + (r0 + 8) * N + col) = p1;
        }
    }
}

// ---------------------------------------------------------------------------
// K1: (b,c,t,h,w) -> LayerNorm over c -> bf16 g_act ; vectorized IO
// ---------------------------------------------------------------------------
#define K1_SMEM (512 * 33 * 4)

__global__ __launch_bounds__(256) void k1_ln(const float* __restrict__ x,
                                             const float* __restrict__ gamma,
                                             const float* __restrict__ beta,
                                             __nv_bfloat16* __restrict__ nrm) {
    extern __shared__ float tile[];
    int bid = blockIdx.x;
    int b = bid >> 9;
    int t = (bid >> 5) & 15;
    int h = bid & 31;
    int tid = threadIdx.x;
    int lane = tid & 31, r = tid >> 5;

    size_t xbase = (size_t)b * (CC * TT * HH * WW) + (size_t)t * (HH * WW) + (size_t)h * WW;

    // load: float4 over w (16 iters)
    #pragma unroll
    for (int it = 0; it < 16; it++) {
        int e = tid + it * 256;
        int cc = e >> 3, w4 = (e & 7) * 4;
        float4 v = *(const float4*)(x + xbase + (size_t)cc * (TT*HH*WW) + w4);
        tile[cc * 33 + w4 + 0] = v.x;
        tile[cc * 33 + w4 + 1] = v.y;
        tile[cc * 33 + w4 + 2] = v.z;
        tile[cc * 33 + w4 + 3] = v.w;
    }
    __syncthreads();

    float s = 0.f, s2 = 0.f;
    for (int cc = r; cc < CC; cc += 8) {
        float v = tile[cc * 33 + lane];
        s += v; s2 += v * v;
    }
    __shared__ float red0[8][32], red1[8][32];
    __shared__ float mu_s[32], rs_s[32];
    red0[r][lane] = s; red1[r][lane] = s2;
    __syncthreads();
    if (tid < 32) {
        float a = 0.f, q = 0.f;
        #pragma unroll
        for (int i = 0; i < 8; i++) { a += red0[i][tid]; q += red1[i][tid]; }
        float mu = a * (1.f / CC);
        float var = q * (1.f / CC) - mu * mu;
        mu_s[tid] = mu;
        rs_s[tid] = rsqrtf(var + 1e-5f);
    }
    __syncthreads();

    size_t obase = ((size_t)(b * 1024 + h * 32) * TT + t) * CC;

    // write: bf16x2 over cc (32 iters)
    #pragma unroll
    for (int it = 0; it < 32; it++) {
        int e = tid + it * 256;
        int ww = e >> 8, c2 = (e & 255) * 2;
        float mu = mu_s[ww], rs = rs_s[ww];
        float v0 = (tile[c2 * 33 + ww] - mu) * rs * __ldg(gamma + c2) + __ldg(beta + c2);
        float v1 = (tile[(c2 + 1) * 33 + ww] - mu) * rs * __ldg(gamma + c2 + 1) + __ldg(beta + c2 + 1);
        __nv_bfloat162 p;
        p.x = __float2bfloat16_rn(v0);
        p.y = __float2bfloat16_rn(v1);
        *(__nv_bfloat162*)(nrm + obase + (size_t)ww * (TT * CC) + c2) = p;
    }
}

// ---------------------------------------------------------------------------
// K3: tensor-core attention; V prefetched up front as raw bf16.
// ---------------------------------------------------------------------------
#define K3_SMEM (108032)
#define OFF_KTAB 0
#define OFF_VTAB 2176
#define OFF_BUFA 4480
#define OFF_BUFB (4480 + 8*1152)              // 13696
#define OFF_VRAW (13696 + 8*1088)             // 22400 (floats)

__global__ __launch_bounds__(256, 2) void k3_attn(const __nv_bfloat16* __restrict__ qkv,
                                                  const float* __restrict__ k_table,
                                                  const float* __restrict__ v_table,
                                                  __nv_bfloat16* __restrict__ aout) {
    extern __shared__ float sm[];
    const int tid = threadIdx.x;
    const int w = tid >> 5, lane = tid & 31;
    const int Bidx = blockIdx.x;
    const int r = lane >> 2, qc = lane & 3;

    float* ktab = sm + OFF_KTAB;
    float* vtab = sm + OFF_VTAB;
    float* bufA = sm + OFF_BUFA + w * 1152;
    float* bufB = sm + OFF_BUFB + w * 1088;
    uint4* vraw = (uint4*)(sm + OFF_VRAW) + w * 144;   // 576 floats = 144 uint4 per warp

    #pragma unroll
    for (int it = 0; it < 8; it++) {
        int e = tid + it * 256;
        int d = e >> 6, c = e & 63;
        float kv = (d < 31) ? k_table[(49 + d) * CH + c] : 0.f;
        float vv = (d < 31) ? v_table[(49 + d) * CH + c] : 0.f;
        ktab[d * 68 + c] = f2tf_f(kv);
        vtab[d * 72 + c] = f2tf_f(vv);
    }

    // stage Q, K (bf16 -> fp32 smem) and V (raw bf16 copy) -- all loads upfront
    const __nv_bfloat16* gq = qkv + (size_t)Bidx * TT * (3 * CC) + w * CH;
    #pragma unroll
    for (int it = 0; it < 4; it++) {
        int idx = lane + it * 32;                  // 0..127
        int row = idx >> 3, c8 = (idx & 7) * 8;
        __nv_bfloat162 vq[4], vk[4];
        *(uint4*)vq = *(const uint4*)(gq + (size_t)row * (3 * CC) + c8);
        *(uint4*)vk = *(const uint4*)(gq + (size_t)row * (3 * CC) + CC + c8);
        vraw[row * 9 + (c8 >> 3)] = *(const uint4*)(gq + (size_t)row * (3 * CC) + 2 * CC + c8);
        #pragma unroll
        for (int u = 0; u < 4; u++) {
            float2 fq = __bfloat1622float2(vq[u]);
            float2 fk = __bfloat1622float2(vk[u]);
            bufA[row * 68 + c8 + 2*u]     = fq.x;
            bufA[row * 68 + c8 + 2*u + 1] = fq.y;
            bufB[row * 68 + c8 + 2*u]     = fk.x;
            bufB[row * 68 + c8 + 2*u + 1] = fk.y;
        }
    }
    __syncthreads();

    float c1[2][4] = {{0.f,0.f,0.f,0.f},{0.f,0.f,0.f,0.f}};
    float c2[4][4] = {{0.f,0.f,0.f,0.f},{0.f,0.f,0.f,0.f},{0.f,0.f,0.f,0.f},{0.f,0.f,0.f,0.f}};
    #pragma unroll
    for (int ks = 0; ks < 8; ks++) {
        const int k0 = ks * 8;
        uint32_t a[4];
        a[0] = __float_as_uint(bufA[r * 68 + k0 + qc]);
        a[1] = __float_as_uint(bufA[(r + 8) * 68 + k0 + qc]);
        a[2] = __float_as_uint(bufA[r * 68 + k0 + qc + 4]);
        a[3] = __float_as_uint(bufA[(r + 8) * 68 + k0 + qc + 4]);
        #pragma unroll
        for (int nb = 0; nb < 2; nb++) {
            uint32_t b0 = __float_as_uint(bufB[(nb * 8 + r) * 68 + k0 + qc]);
            uint32_t b1 = __float_as_uint(bufB[(nb * 8 + r) * 68 + k0 + qc + 4]);
            mma_tf32(c1[nb], a, b0, b1);
        }
        #pragma unroll
        for (int nb = 0; nb < 4; nb++) {
            uint32_t b0 = __float_as_uint(ktab[(nb * 8 + r) * 68 + k0 + qc]);
            uint32_t b1 = __float_as_uint(ktab[(nb * 8 + r) * 68 + k0 + qc + 4]);
            mma_tf32(c2[nb], a, b0, b1);
        }
    }
    __syncwarp();

    #pragma unroll
    for (int nb = 0; nb < 4; nb++) {
        #pragma unroll
        for (int q = 0; q < 4; q++) {
            int row = r + (q >> 1) * 8;
            int col = nb * 8 + 2 * qc + (q & 1);
            bufA[row * 33 + col] = c2[nb][q];
        }
    }
    #pragma unroll
    for (int it = 0; it < 28; it++)
        bufB[lane + it * 32] = 0.f;
    __syncwarp();

    float attv[2][4];
    #pragma unroll
    for (int h = 0; h < 2; h++) {
        int row = r + 8 * h;
        float v[4];
        #pragma unroll
        for (int m = 0; m < 4; m++) {
            int nb = m >> 1;
            int j = nb * 8 + 2 * qc + (m & 1);
            v[m] = (c1[nb][h * 2 + (m & 1)] + bufA[row * 33 + (j - row + 15)]) * 0.125f;
        }
        float mx = fmaxf(fmaxf(v[0], v[1]), fmaxf(v[2], v[3]));
        mx = fmaxf(mx, __shfl_xor_sync(0xffffffffu, mx, 1));
        mx = fmaxf(mx, __shfl_xor_sync(0xffffffffu, mx, 2));
        float sum = 0.f;
        #pragma unroll
        for (int m = 0; m < 4; m++) { v[m] = __expf(v[m] - mx); sum += v[m]; }
        sum += __shfl_xor_sync(0xffffffffu, sum, 1);
        sum += __shfl_xor_sync(0xffffffffu, sum, 2);
        float inv = 1.f / sum;
        #pragma unroll
        for (int m = 0; m < 4; m++) attv[h][m] = f2tf_f(v[m] * inv);
    }
    __syncwarp();

    #pragma unroll
    for (int h = 0; h < 2; h++) {
        int row = r + 8 * h;
        #pragma unroll
        for (int m = 0; m < 4; m++) {
            int j = (m >> 1) * 8 + 2 * qc + (m & 1);
            bufB[row * 20 + j] = attv[h][m];
            bufB[320 + row * 36 + (j - row + 15)] = attv[h][m];
        }
    }

    // convert prefetched V: bf16 raw -> fp32 bufA [16][72]
    #pragma unroll
    for (int it = 0; it < 4; it++) {
        int idx = lane + it * 32;
        int row = idx >> 3, c8 = (idx & 7) * 8;
        __nv_bfloat162 vv[4];
        *(uint4*)vv = vraw[row * 9 + (c8 >> 3)];
        float4 lo, hi;
        float2 f0 = __bfloat1622float2(vv[0]);
        float2 f1 = __bfloat1622float2(vv[1]);
        float2 f2 = __bfloat1622float2(vv[2]);
        float2 f3 = __bfloat1622float2(vv[3]);
        lo = make_float4(f0.x, f0.y, f1.x, f1.y);
        hi = make_float4(f2.x, f2.y, f3.x, f3.y);
        *(float4*)(bufA + row * 72 + c8)     = lo;
        *(float4*)(bufA + row * 72 + c8 + 4) = hi;
    }
    __syncwarp();

    uint32_t aS[2][4], aS2[4][4];
    #pragma unroll
    for (int ks = 0; ks < 2; ks++) {
        aS[ks][0] = __float_as_uint(bufB[r * 20 + ks * 8 + qc]);
        aS[ks][1] = __float_as_uint(bufB[(r + 8) * 20 + ks * 8 + qc]);
        aS[ks][2] = __float_as_uint(bufB[r * 20 + ks * 8 + qc + 4]);
        aS[ks][3] = __float_as_uint(bufB[(r + 8) * 20 + ks * 8 + qc + 4]);
    }
    #pragma unroll
    for (int ks = 0; ks < 4; ks++) {
        aS2[ks][0] = __float_as_uint(bufB[320 + r * 36 + ks * 8 + qc]);
        aS2[ks][1] = __float_as_uint(bufB[320 + (r + 8) * 36 + ks * 8 + qc]);
        aS2[ks][2] = __float_as_uint(bufB[320 + r * 36 + ks * 8 + qc + 4]);
        aS2[ks][3] = __float_as_uint(bufB[320 + (r + 8) * 36 + ks * 8 + qc + 4]);
    }

    __nv_bfloat16* ga = aout + (size_t)(Bidx * TT) * CC + w * CH;
    #pragma unroll
    for (int nb = 0; nb < 8; nb++) {
        float o[4] = {0.f, 0.f, 0.f, 0.f};
        #pragma unroll
        for (int ks = 0; ks < 2; ks++) {
            uint32_t b0 = __float_as_uint(bufA[(ks * 8 + qc) * 72 + nb * 8 + r]);
            uint32_t b1 = __float_as_uint(bufA[(ks * 8 + qc + 4) * 72 + nb * 8 + r]);
            mma_tf32(o, aS[ks], b0, b1);
        }
        #pragma unroll
        for (int ks = 0; ks < 4; ks++) {
            uint32_t b0 = __float_as_uint(vtab[(ks * 8 + qc) * 72 + nb * 8 + r]);
            uint32_t b1 = __float_as_uint(vtab[(ks * 8 + qc + 4) * 72 + nb * 8 + r]);
            mma_tf32(o, aS2[ks], b0, b1);
        }
        int col = nb * 8 + 2 * qc;
        __nv_bfloat162 p0, p1;
        p0.x = __float2bfloat16_rn(o[0]); p0.y = __float2bfloat16_rn(o[1]);
        p1.x = __float2bfloat16_rn(o[2]); p1.y = __float2bfloat16_rn(o[3]);
        *(__nv_bfloat162*)(ga + (size_t)r * CC + col)       = p0;
        *(__nv_bfloat162*)(ga + (size_t)(r + 8) * CC + col) = p1;
    }
}

// ---------------------------------------------------------------------------
// K5: out = x + transpose-back(proj_seq bf16)
// ---------------------------------------------------------------------------
__global__ __launch_bounds__(256) void k5_resid(const float* __restrict__ x,
                                                const __nv_bfloat16* __restrict__ oseq,
                                                float* __restrict__ out) {
    int bid = blockIdx.x;
    int b = bid >> 9;
    int t = (bid >> 5) & 15;
    int h = bid & 31;
    int tid = threadIdx.x;

    size_t base  = (size_t)b * (CC * TT * HH * WW) + (size_t)t * (HH * WW) + (size_t)h * WW;
    size_t obase = ((size_t)(b * 1024 + h * 32) * TT + t) * CC;

    __shared__ float tile[128 * 33];
    for (int c0 = 0; c0 < CC; c0 += 128) {
        __syncthreads();
        for (int e = tid; e < 128 * 32; e += 256) {
            int ww = e >> 7, cc = e & 127;
            tile[cc * 33 + ww] = __bfloat162float(oseq[obase + (size_t)ww * (TT * CC) + c0 + cc]);
        }
        __syncthreads();
        for (int e = tid; e < 128 * 32; e += 256) {
            int cc = e >> 5, ww = e & 31;
            size_t gi = base + (size_t)(c0 + cc) * (TT*HH*WW) + ww;
            out[gi] = x[gi] + tile[cc * 33 + ww];
        }
    }
}

// ---------------------------------------------------------------------------
extern "C" void kernel_launch(void* const* d_in, const int* in_sizes, int n_in,
                              void* d_out, int out_size) {
    const float* x       = (const float*)d_in[0];
    const float* ln_g    = (const float*)d_in[1];
    const float* ln_b    = (const float*)d_in[2];
    const float* qkv_w   = (const float*)d_in[3];
    const float* qkv_b   = (const float*)d_in[4];
    const float* k_table = (const float*)d_in[5];
    const float* v_table = (const float*)d_in[6];
    const float* proj_w  = (const float*)d_in[7];
    const float* proj_b  = (const float*)d_in[8];
    float* out = (float*)d_out;

    void *p_act_v, *p_qkv_v, *p_attb_v, *p_proj_v, *p_wq_v, *p_wp_v;
    cudaGetSymbolAddress(&p_act_v, g_act);
    cudaGetSymbolAddress(&p_qkv_v, g_qkv);
    cudaGetSymbolAddress(&p_attb_v, g_attb);
    cudaGetSymbolAddress(&p_proj_v, g_proj);
    cudaGetSymbolAddress(&p_wq_v, g_wq);
    cudaGetSymbolAddress(&p_wp_v, g_wp);
    __nv_bfloat16* p_act  = (__nv_bfloat16*)p_act_v;
    __nv_bfloat16* p_qkv  = (__nv_bfloat16*)p_qkv_v;
    __nv_bfloat16* p_attb = (__nv_bfloat16*)p_attb_v;
    __nv_bfloat16* p_proj = (__nv_bfloat16*)p_proj_v;
    __nv_bfloat16* p_wq   = (__nv_bfloat16*)p_wq_v;
    __nv_bfloat16* p_wp   = (__nv_bfloat16*)p_wp_v;

    cudaFuncSetAttribute(tc_gemm, cudaFuncAttributeMaxDynamicSharedMemorySize, GSMEM_SZ);
    cudaFuncSetAttribute(k1_ln, cudaFuncAttributeMaxDynamicSharedMemorySize, K1_SMEM);
    cudaFuncSetAttribute(k3_attn, cudaFuncAttributeMaxDynamicSharedMemorySize, K3_SMEM);

    wcvt<<<(3 * CC * CC + 255) / 256, 256>>>(qkv_w, proj_w, p_wq, p_wp);

    k1_ln<<<BB * TT * HH, 256, K1_SMEM>>>(x, ln_g, ln_b, p_act);

    {
        dim3 grid(3 * CC / 128, ROWS / 128);
        tc_gemm<<<grid, 256, GSMEM_SZ>>>(p_act, p_wq, qkv_b, p_qkv, ROWS, 3 * CC);
    }

    k3_attn<<<BSEQ, 256, K3_SMEM>>>(p_qkv, k_table, v_table, p_attb);

    {
        dim3 grid(CC / 128, ROWS / 128);
        tc_gemm<<<grid, 256, GSMEM_SZ>>>(p_attb, p_wp, proj_b, p_proj, ROWS, CC);
    }

    k5_resid<<<BB * TT * HH, 256>>>(x, p_proj, out);
}

// round 12
// speedup vs baseline: 1.1688x; 1.1688x over previous
#include <cuda_runtime.h>
#include <cuda_bf16.h>
#include <cstdint>

#define BB   2
#define CC   512
#define TT   16
#define HH   32
#define WW   32
#define NH   8
#define CH   64
#define BSEQ (BB*HH*WW)     // 2048
#define ROWS (BSEQ*TT)      // 32768
#define GK   512

// Row layout for all seq tensors: row = (b*16 + t)*1024 + h*32 + w
__device__ __nv_bfloat16 g_act[(size_t)ROWS * CC];
__device__ __nv_bfloat16 g_qkv[(size_t)ROWS * 3 * CC];
__device__ __nv_bfloat16 g_attb[(size_t)ROWS * CC];
__device__ __nv_bfloat16 g_wq[(size_t)3 * CC * CC];
__device__ __nv_bfloat16 g_wp[(size_t)CC * CC];

// ---------------------------------------------------------------------------
__device__ __forceinline__ uint32_t smem_u32(const void* p) {
    uint32_t a;
    asm("{ .reg .u64 t; cvta.to.shared.u64 t, %1; cvt.u32.u64 %0, t; }" : "=r"(a) : "l"(p));
    return a;
}
#define SWZ(o) ((o) ^ ((((uint32_t)(o)) >> 3) & 0x70))

__device__ __forceinline__ void cpasync16(uint32_t dst, const void* src) {
    asm volatile("cp.async.cg.shared.global [%0], [%1], 16;" :: "r"(dst), "l"(src));
}
__device__ __forceinline__ void ldsm_x4(uint32_t* r, uint32_t addr) {
    asm volatile("ldmatrix.sync.aligned.m8n8.x4.shared.b16 {%0,%1,%2,%3}, [%4];"
                 : "=r"(r[0]), "=r"(r[1]), "=r"(r[2]), "=r"(r[3]) : "r"(addr));
}
__device__ __forceinline__ float f2tf_f(float x) {
    uint32_t y;
    asm("cvt.rna.tf32.f32 %0, %1;" : "=r"(y) : "r"(__float_as_uint(x)));
    return __uint_as_float(y);
}
__device__ __forceinline__ void mma_tf32(float* c, const uint32_t* a, uint32_t b0, uint32_t b1) {
    asm volatile(
        "mma.sync.aligned.m16n8k8.row.col.f32.tf32.tf32.f32 "
        "{%0,%1,%2,%3}, {%4,%5,%6,%7}, {%8,%9}, {%0,%1,%2,%3};"
        : "+f"(c[0]), "+f"(c[1]), "+f"(c[2]), "+f"(c[3])
        : "r"(a[0]), "r"(a[1]), "r"(a[2]), "r"(a[3]), "r"(b0), "r"(b1));
}
__device__ __forceinline__ void mma_bf16(float* c, const uint32_t* a, uint32_t b0, uint32_t b1) {
    asm volatile(
        "mma.sync.aligned.m16n8k16.row.col.f32.bf16.bf16.f32 "
        "{%0,%1,%2,%3}, {%4,%5,%6,%7}, {%8,%9}, {%0,%1,%2,%3};"
        : "+f"(c[0]), "+f"(c[1]), "+f"(c[2]), "+f"(c[3])
        : "r"(a[0]), "r"(a[1]), "r"(a[2]), "r"(a[3]), "r"(b0), "r"(b1));
}

// ---------------------------------------------------------------------------
__global__ __launch_bounds__(256) void wcvt(const float* __restrict__ qkv_w,
                                            const float* __restrict__ proj_w,
                                            __nv_bfloat16* __restrict__ wq,
                                            __nv_bfloat16* __restrict__ wp) {
    int i = blockIdx.x * 256 + threadIdx.x;
    if (i < 3 * CC * CC) wq[i] = __float2bfloat16_rn(qkv_w[i]);
    if (i < CC * CC)     wp[i] = __float2bfloat16_rn(proj_w[i]);
}

// ---------------------------------------------------------------------------
// Shared GEMM mainloop pieces
// ---------------------------------------------------------------------------
#define NSTAGE   3
#define STAGE_SZ 32768
#define GSMEM_SZ (NSTAGE*STAGE_SZ)
#define NCH      (GK >> 6)          // 8

// BF16 GEMM-NT, bf16 output (qkv)
__global__ __launch_bounds__(256, 2) void tc_gemm(const __nv_bfloat16* __restrict__ A,
                                                  const __nv_bfloat16* __restrict__ W,
                                                  const float* __restrict__ bias,
                                                  __nv_bfloat16* __restrict__ C,
                                                  int M, int N) {
    extern __shared__ __align__(1024) char smraw[];
    const uint32_t base = smem_u32(smraw);

    const int tid  = threadIdx.x;
    const int wid  = tid >> 5, lane = tid & 31;
    const int wm   = wid & 1, wn = wid >> 1;
    const int bn   = blockIdx.x, bm = blockIdx.y;

    uint32_t st_off[4];
    const __nv_bfloat16* ga[4];
    const __nv_bfloat16* gw[4];
    #pragma unroll
    for (int it = 0; it < 4; it++) {
        int idx = tid + it * 256;
        int r = idx >> 3, c16 = idx & 7;
        st_off[it] = SWZ((uint32_t)(r * 128 + c16 * 16));
        ga[it] = A + (size_t)(bm * 128 + r) * GK + c16 * 8;
        gw[it] = W + (size_t)(bn * 128 + r) * GK + c16 * 8;
    }

    auto load_chunk = [&](int l) {
        const int k0 = l << 6;
        const uint32_t sA = base + (l % NSTAGE) * STAGE_SZ;
        const uint32_t sB = sA + 16384;
        #pragma unroll
        for (int it = 0; it < 4; it++) {
            cpasync16(sA + st_off[it], ga[it] + k0);
            cpasync16(sB + st_off[it], gw[it] + k0);
        }
        asm volatile("cp.async.commit_group;" ::: "memory");
    };

    load_chunk(0);
    load_chunk(1);

    const int m_row_in = ((lane >> 3) & 1) * 8 + (lane & 7);
    const int m_kb     = (lane >> 4) * 16;
    uint32_t a_off[4], b_off[2];
    #pragma unroll
    for (int f = 0; f < 4; f++) {
        int row = wm * 64 + f * 16 + m_row_in;
        a_off[f] = (uint32_t)(row * 128 + (m_kb ^ ((row & 7) << 4)));
    }
    #pragma unroll
    for (int p = 0; p < 2; p++) {
        int row = wn * 32 + p * 16 + m_row_in;
        b_off[p] = (uint32_t)(row * 128 + (m_kb ^ ((row & 7) << 4)));
    }

    float acc[4][4][4];
    #pragma unroll
    for (int f = 0; f < 4; f++)
        #pragma unroll
        for (int g = 0; g < 4; g++)
            #pragma unroll
            for (int r = 0; r < 4; r++) acc[f][g][r] = 0.f;

    #pragma unroll
    for (int c = 0; c < NCH; c++) {
        asm volatile("cp.async.wait_group 1;" ::: "memory");
        __syncthreads();
        if (c + 2 < NCH) load_chunk(c + 2);

        const uint32_t sA = base + (c % NSTAGE) * STAGE_SZ;
        const uint32_t sB = sA + 16384;
        #pragma unroll
        for (int ks = 0; ks < 4; ks++) {
            uint32_t a[4][4], b[2][4];
            #pragma unroll
            for (int f = 0; f < 4; f++)
                ldsm_x4(a[f], sA + (a_off[f] ^ (ks << 5)));
            #pragma unroll
            for (int p = 0; p < 2; p++)
                ldsm_x4(b[p], sB + (b_off[p] ^ (ks << 5)));
            #pragma unroll
            for (int f = 0; f < 4; f++)
                #pragma unroll
                for (int g = 0; g < 4; g++)
                    mma_bf16(acc[f][g], a[f], b[g >> 1][g & 1], b[g >> 1][(g & 1) + 2]);
        }
        __syncthreads();
    }

    const int col_in = 2 * (lane & 3);
    #pragma unroll
    for (int g = 0; g < 4; g++) {
        const int col = bn * 128 + wn * 32 + g * 8 + col_in;
        const float b0 = bias[col], b1 = bias[col + 1];
        #pragma unroll
        for (int f = 0; f < 4; f++) {
            const size_t r0 = (size_t)bm * 128 + wm * 64 + f * 16 + (lane >> 2);
            __nv_bfloat162 p0, p1;
            p0.x = __float2bfloat16_rn(acc[f][g][0] + b0);
            p0.y = __float2bfloat16_rn(acc[f][g][1] + b1);
            p1.x = __float2bfloat16_rn(acc[f][g][2] + b0);
            p1.y = __float2bfloat16_rn(acc[f][g][3] + b1);
            *(__nv_bfloat162*)(C + r0 * N + col)       = p0;
            *(__nv_bfloat162*)(C + (r0 + 8) * N + col) = p1;
        }
    }
}

// ---------------------------------------------------------------------------
// Proj GEMM fused with residual + transpose-back. N=CC.
// bm -> b = bm>>7, t = (bm&127)>>3, hw0 = (bm&7)*128.
// out[b,c,t,hw] = x[...] + (A@W^T + bias); smem-transposed, coalesced stores.
// ---------------------------------------------------------------------------
__global__ __launch_bounds__(256, 2) void tc_gemm_resid(const __nv_bfloat16* __restrict__ A,
                                                        const __nv_bfloat16* __restrict__ W,
                                                        const float* __restrict__ bias,
                                                        const float* __restrict__ x,
                                                        float* __restrict__ out) {
    extern __shared__ __align__(1024) char smraw[];
    const uint32_t base = smem_u32(smraw);

    const int tid  = threadIdx.x;
    const int wid  = tid >> 5, lane = tid & 31;
    const int wm   = wid & 1, wn = wid >> 1;
    const int bn   = blockIdx.x, bm = blockIdx.y;

    uint32_t st_off[4];
    const __nv_bfloat16* ga[4];
    const __nv_bfloat16* gw[4];
    #pragma unroll
    for (int it = 0; it < 4; it++) {
        int idx = tid + it * 256;
        int r = idx >> 3, c16 = idx & 7;
        st_off[it] = SWZ((uint32_t)(r * 128 + c16 * 16));
        ga[it] = A + (size_t)(bm * 128 + r) * GK + c16 * 8;
        gw[it] = W + (size_t)(bn * 128 + r) * GK + c16 * 8;
    }

    auto load_chunk = [&](int l) {
        const int k0 = l << 6;
        const uint32_t sA = base + (l % NSTAGE) * STAGE_SZ;
        const uint32_t sB = sA + 16384;
        #pragma unroll
        for (int it = 0; it < 4; it++) {
            cpasync16(sA + st_off[it], ga[it] + k0);
            cpasync16(sB + st_off[it], gw[it] + k0);
        }
        asm volatile("cp.async.commit_group;" ::: "memory");
    };

    load_chunk(0);
    load_chunk(1);

    const int m_row_in = ((lane >> 3) & 1) * 8 + (lane & 7);
    const int m_kb     = (lane >> 4) * 16;
    uint32_t a_off[4], b_off[2];
    #pragma unroll
    for (int f = 0; f < 4; f++) {
        int row = wm * 64 + f * 16 + m_row_in;
        a_off[f] = (uint32_t)(row * 128 + (m_kb ^ ((row & 7) << 4)));
    }
    #pragma unroll
    for (int p = 0; p < 2; p++) {
        int row = wn * 32 + p * 16 + m_row_in;
        b_off[p] = (uint32_t)(row * 128 + (m_kb ^ ((row & 7) << 4)));
    }

    float acc[4][4][4];
    #pragma unroll
    for (int f = 0; f < 4; f++)
        #pragma unroll
        for (int g = 0; g < 4; g++)
            #pragma unroll
            for (int r = 0; r < 4; r++) acc[f][g][r] = 0.f;

    #pragma unroll
    for (int c = 0; c < NCH; c++) {
        asm volatile("cp.async.wait_group 1;" ::: "memory");
        __syncthreads();
        if (c + 2 < NCH) load_chunk(c + 2);

        const uint32_t sA = base + (c % NSTAGE) * STAGE_SZ;
        const uint32_t sB = sA + 16384;
        #pragma unroll
        for (int ks = 0; ks < 4; ks++) {
            uint32_t a[4][4], b[2][4];
            #pragma unroll
            for (int f = 0; f < 4; f++)
                ldsm_x4(a[f], sA + (a_off[f] ^ (ks << 5)));
            #pragma unroll
            for (int p = 0; p < 2; p++)
                ldsm_x4(b[p], sB + (b_off[p] ^ (ks << 5)));
            #pragma unroll
            for (int f = 0; f < 4; f++)
                #pragma unroll
                for (int g = 0; g < 4; g++)
                    mma_bf16(acc[f][g], a[f], b[g >> 1][g & 1], b[g >> 1][(g & 1) + 2]);
        }
        __syncthreads();
    }

    // ---- epilogue: T[m][n] (stride 129), then coalesced residual writes
    float* T = (float*)smraw;
    const int col_in = 2 * (lane & 3);
    #pragma unroll
    for (int g = 0; g < 4; g++) {
        const int cl = wn * 32 + g * 8 + col_in;
        const float b0 = bias[bn * 128 + cl], b1 = bias[bn * 128 + cl + 1];
        #pragma unroll
        for (int f = 0; f < 4; f++) {
            const int m0 = wm * 64 + f * 16 + (lane >> 2);
            T[m0 * 129 + cl]           = acc[f][g][0] + b0;
            T[m0 * 129 + cl + 1]       = acc[f][g][1] + b1;
            T[(m0 + 8) * 129 + cl]     = acc[f][g][2] + b0;
            T[(m0 + 8) * 129 + cl + 1] = acc[f][g][3] + b1;
        }
    }
    __syncthreads();

    const int bb  = bm >> 7;
    const int rem = bm & 127;
    const int tt  = rem >> 3;
    const int hw0 = (rem & 7) * 128;
    const size_t obase = (size_t)bb * (CC * TT * HH * WW) + (size_t)tt * (HH * WW) + hw0;

    #pragma unroll
    for (int it = 0; it < 16; it++) {
        int q = tid + it * 256;        // 0..4095
        int n = q >> 5;                // 0..127 (channel within tile)
        int m0 = q & 31;
        size_t gcol = obase + (size_t)(bn * 128 + n) * (TT * HH * WW) + m0;
        #pragma unroll
        for (int u = 0; u < 4; u++) {
            int m = m0 + u * 32;
            out[gcol + u * 32] = x[gcol + u * 32] + T[m * 129 + n];
        }
    }
}

// ---------------------------------------------------------------------------
// K1: (b,c,t,h,w) -> LayerNorm over c -> bf16 g_act, rows (b*16+t)*1024+h*32+w
// ---------------------------------------------------------------------------
#define K1_SMEM (512 * 33 * 4)

__global__ __launch_bounds__(256) void k1_ln(const float* __restrict__ x,
                                             const float* __restrict__ gamma,
                                             const float* __restrict__ beta,
                                             __nv_bfloat16* __restrict__ nrm) {
    extern __shared__ float tile[];
    int bid = blockIdx.x;
    int b = bid >> 9;
    int t = (bid >> 5) & 15;
    int h = bid & 31;
    int tid = threadIdx.x;
    int lane = tid & 31, r = tid >> 5;

    size_t xbase = (size_t)b * (CC * TT * HH * WW) + (size_t)t * (HH * WW) + (size_t)h * WW;

    #pragma unroll
    for (int it = 0; it < 16; it++) {
        int e = tid + it * 256;
        int cc = e >> 3, w4 = (e & 7) * 4;
        float4 v = *(const float4*)(x + xbase + (size_t)cc * (TT*HH*WW) + w4);
        tile[cc * 33 + w4 + 0] = v.x;
        tile[cc * 33 + w4 + 1] = v.y;
        tile[cc * 33 + w4 + 2] = v.z;
        tile[cc * 33 + w4 + 3] = v.w;
    }
    __syncthreads();

    float s = 0.f, s2 = 0.f;
    for (int cc = r; cc < CC; cc += 8) {
        float v = tile[cc * 33 + lane];
        s += v; s2 += v * v;
    }
    __shared__ float red0[8][32], red1[8][32];
    __shared__ float mu_s[32], rs_s[32];
    red0[r][lane] = s; red1[r][lane] = s2;
    __syncthreads();
    if (tid < 32) {
        float a = 0.f, q = 0.f;
        #pragma unroll
        for (int i = 0; i < 8; i++) { a += red0[i][tid]; q += red1[i][tid]; }
        float mu = a * (1.f / CC);
        float var = q * (1.f / CC) - mu * mu;
        mu_s[tid] = mu;
        rs_s[tid] = rsqrtf(var + 1e-5f);
    }
    __syncthreads();

    size_t obase = ((size_t)((b * 16 + t) * 1024 + h * 32)) * CC;

    #pragma unroll
    for (int it = 0; it < 32; it++) {
        int e = tid + it * 256;
        int ww = e >> 8, c2 = (e & 255) * 2;
        float mu = mu_s[ww], rs = rs_s[ww];
        float v0 = (tile[c2 * 33 + ww] - mu) * rs * __ldg(gamma + c2) + __ldg(beta + c2);
        float v1 = (tile[(c2 + 1) * 33 + ww] - mu) * rs * __ldg(gamma + c2 + 1) + __ldg(beta + c2 + 1);
        __nv_bfloat162 p;
        p.x = __float2bfloat16_rn(v0);
        p.y = __float2bfloat16_rn(v1);
        *(__nv_bfloat162*)(nrm + obase + (size_t)ww * CC + c2) = p;
    }
}

// ---------------------------------------------------------------------------
// K3: tensor-core attention (round-9 structure); rows strided by 1024.
// ---------------------------------------------------------------------------
#define K3_SMEM (89600)
#define OFF_KTAB 0
#define OFF_VTAB 2176
#define OFF_BUFA 4480
#define OFF_BUFB (4480 + 8*1152)
#define QROW ((size_t)1024 * 3 * CC)
#define OROW ((size_t)1024 * CC)

__global__ __launch_bounds__(256, 2) void k3_attn(const __nv_bfloat16* __restrict__ qkv,
                                                  const float* __restrict__ k_table,
                                                  const float* __restrict__ v_table,
                                                  __nv_bfloat16* __restrict__ aout) {
    extern __shared__ float sm[];
    const int tid = threadIdx.x;
    const int w = tid >> 5, lane = tid & 31;
    const int Bidx = blockIdx.x;
    const int b = Bidx >> 10, hw = Bidx & 1023;
    const int r = lane >> 2, qc = lane & 3;

    float* ktab = sm + OFF_KTAB;
    float* vtab = sm + OFF_VTAB;
    float* bufA = sm + OFF_BUFA + w * 1152;
    float* bufB = sm + OFF_BUFB + w * 1088;

    #pragma unroll
    for (int it = 0; it < 8; it++) {
        int e = tid + it * 256;
        int d = e >> 6, c = e & 63;
        float kv = (d < 31) ? k_table[(49 + d) * CH + c] : 0.f;
        float vv = (d < 31) ? v_table[(49 + d) * CH + c] : 0.f;
        ktab[d * 68 + c] = f2tf_f(kv);
        vtab[d * 72 + c] = f2tf_f(vv);
    }

    const __nv_bfloat16* gq = qkv + ((size_t)b * 16384 + hw) * (3 * CC) + w * CH;
    #pragma unroll
    for (int it = 0; it < 4; it++) {
        int idx = lane + it * 32;
        int row = idx >> 3, c8 = (idx & 7) * 8;
        __nv_bfloat162 vq[4], vk[4];
        *(uint4*)vq = *(const uint4*)(gq + (size_t)row * QROW + c8);
        *(uint4*)vk = *(const uint4*)(gq + (size_t)row * QROW + CC + c8);
        #pragma unroll
        for (int u = 0; u < 4; u++) {
            float2 fq = __bfloat1622float2(vq[u]);
            float2 fk = __bfloat1622float2(vk[u]);
            bufA[row * 68 + c8 + 2*u]     = fq.x;
            bufA[row * 68 + c8 + 2*u + 1] = fq.y;
            bufB[row * 68 + c8 + 2*u]     = fk.x;
            bufB[row * 68 + c8 + 2*u + 1] = fk.y;
        }
    }
    __syncthreads();

    float c1[2][4] = {{0.f,0.f,0.f,0.f},{0.f,0.f,0.f,0.f}};
    float c2[4][4] = {{0.f,0.f,0.f,0.f},{0.f,0.f,0.f,0.f},{0.f,0.f,0.f,0.f},{0.f,0.f,0.f,0.f}};
    #pragma unroll
    for (int ks = 0; ks < 8; ks++) {
        const int k0 = ks * 8;
        uint32_t a[4];
        a[0] = __float_as_uint(bufA[r * 68 + k0 + qc]);
        a[1] = __float_as_uint(bufA[(r + 8) * 68 + k0 + qc]);
        a[2] = __float_as_uint(bufA[r * 68 + k0 + qc + 4]);
        a[3] = __float_as_uint(bufA[(r + 8) * 68 + k0 + qc + 4]);
        #pragma unroll
        for (int nb = 0; nb < 2; nb++) {
            uint32_t b0 = __float_as_uint(bufB[(nb * 8 + r) * 68 + k0 + qc]);
            uint32_t b1 = __float_as_uint(bufB[(nb * 8 + r) * 68 + k0 + qc + 4]);
            mma_tf32(c1[nb], a, b0, b1);
        }
        #pragma unroll
        for (int nb = 0; nb < 4; nb++) {
            uint32_t b0 = __float_as_uint(ktab[(nb * 8 + r) * 68 + k0 + qc]);
            uint32_t b1 = __float_as_uint(ktab[(nb * 8 + r) * 68 + k0 + qc + 4]);
            mma_tf32(c2[nb], a, b0, b1);
        }
    }
    __syncwarp();

    #pragma unroll
    for (int nb = 0; nb < 4; nb++) {
        #pragma unroll
        for (int q = 0; q < 4; q++) {
            int row = r + (q >> 1) * 8;
            int col = nb * 8 + 2 * qc + (q & 1);
            bufA[row * 33 + col] = c2[nb][q];
        }
    }
    #pragma unroll
    for (int it = 0; it < 28; it++)
        bufB[lane + it * 32] = 0.f;
    __syncwarp();

    float attv[2][4];
    #pragma unroll
    for (int h = 0; h < 2; h++) {
        int row = r + 8 * h;
        float v[4];
        #pragma unroll
        for (int m = 0; m < 4; m++) {
            int nb = m >> 1;
            int j = nb * 8 + 2 * qc + (m & 1);
            v[m] = (c1[nb][h * 2 + (m & 1)] + bufA[row * 33 + (j - row + 15)]) * 0.125f;
        }
        float mx = fmaxf(fmaxf(v[0], v[1]), fmaxf(v[2], v[3]));
        mx = fmaxf(mx, __shfl_xor_sync(0xffffffffu, mx, 1));
        mx = fmaxf(mx, __shfl_xor_sync(0xffffffffu, mx, 2));
        float sum = 0.f;
        #pragma unroll
        for (int m = 0; m < 4; m++) { v[m] = __expf(v[m] - mx); sum += v[m]; }
        sum += __shfl_xor_sync(0xffffffffu, sum, 1);
        sum += __shfl_xor_sync(0xffffffffu, sum, 2);
        float inv = 1.f / sum;
        #pragma unroll
        for (int m = 0; m < 4; m++) attv[h][m] = f2tf_f(v[m] * inv);
    }
    __syncwarp();

    #pragma unroll
    for (int h = 0; h < 2; h++) {
        int row = r + 8 * h;
        #pragma unroll
        for (int m = 0; m < 4; m++) {
            int j = (m >> 1) * 8 + 2 * qc + (m & 1);
            bufB[row * 20 + j] = attv[h][m];
            bufB[320 + row * 36 + (j - row + 15)] = attv[h][m];
        }
    }

    // stage V (bf16 -> fp32 smem) after softmax
    #pragma unroll
    for (int it = 0; it < 4; it++) {
        int idx = lane + it * 32;
        int row = idx >> 3, c8 = (idx & 7) * 8;
        __nv_bfloat162 vv[4];
        *(uint4*)vv = *(const uint4*)(gq + (size_t)row * QROW + 2 * CC + c8);
        #pragma unroll
        for (int u = 0; u < 4; u++) {
            float2 fv = __bfloat1622float2(vv[u]);
            bufA[row * 72 + c8 + 2*u]     = fv.x;
            bufA[row * 72 + c8 + 2*u + 1] = fv.y;
        }
    }
    __syncwarp();

    uint32_t aS[2][4], aS2[4][4];
    #pragma unroll
    for (int ks = 0; ks < 2; ks++) {
        aS[ks][0] = __float_as_uint(bufB[r * 20 + ks * 8 + qc]);
        aS[ks][1] = __float_as_uint(bufB[(r + 8) * 20 + ks * 8 + qc]);
        aS[ks][2] = __float_as_uint(bufB[r * 20 + ks * 8 + qc + 4]);
        aS[ks][3] = __float_as_uint(bufB[(r + 8) * 20 + ks * 8 + qc + 4]);
    }
    #pragma unroll
    for (int ks = 0; ks < 4; ks++) {
        aS2[ks][0] = __float_as_uint(bufB[320 + r * 36 + ks * 8 + qc]);
        aS2[ks][1] = __float_as_uint(bufB[320 + (r + 8) * 36 + ks * 8 + qc]);
        aS2[ks][2] = __float_as_uint(bufB[320 + r * 36 + ks * 8 + qc + 4]);
        aS2[ks][3] = __float_as_uint(bufB[320 + (r + 8) * 36 + ks * 8 + qc + 4]);
    }

    __nv_bfloat16* gaOut = aout + ((size_t)b * 16384 + hw) * CC + w * CH;
    #pragma unroll
    for (int nb = 0; nb < 8; nb++) {
        float o[4] = {0.f, 0.f, 0.f, 0.f};
        #pragma unroll
        for (int ks = 0; ks < 2; ks++) {
            uint32_t b0 = __float_as_uint(bufA[(ks * 8 + qc) * 72 + nb * 8 + r]);
            uint32_t b1 = __float_as_uint(bufA[(ks * 8 + qc + 4) * 72 + nb * 8 + r]);
            mma_tf32(o, aS[ks], b0, b1);
        }
        #pragma unroll
        for (int ks = 0; ks < 4; ks++) {
            uint32_t b0 = __float_as_uint(vtab[(ks * 8 + qc) * 72 + nb * 8 + r]);
            uint32_t b1 = __float_as_uint(vtab[(ks * 8 + qc + 4) * 72 + nb * 8 + r]);
            mma_tf32(o, aS2[ks], b0, b1);
        }
        int col = nb * 8 + 2 * qc;
        __nv_bfloat162 p0, p1;
        p0.x = __float2bfloat16_rn(o[0]); p0.y = __float2bfloat16_rn(o[1]);
        p1.x = __float2bfloat16_rn(o[2]); p1.y = __float2bfloat16_rn(o[3]);
        *(__nv_bfloat162*)(gaOut + (size_t)r * OROW + col)       = p0;
        *(__nv_bfloat162*)(gaOut + (size_t)(r + 8) * OROW + col) = p1;
    }
}

// ---------------------------------------------------------------------------
extern "C" void kernel_launch(void* const* d_in, const int* in_sizes, int n_in,
                              void* d_out, int out_size) {
    const float* x       = (const float*)d_in[0];
    const float* ln_g    = (const float*)d_in[1];
    const float* ln_b    = (const float*)d_in[2];
    const float* qkv_w   = (const float*)d_in[3];
    const float* qkv_b   = (const float*)d_in[4];
    const float* k_table = (const float*)d_in[5];
    const float* v_table = (const float*)d_in[6];
    const float* proj_w  = (const float*)d_in[7];
    const float* proj_b  = (const float*)d_in[8];
    float* out = (float*)d_out;

    void *p_act_v, *p_qkv_v, *p_attb_v, *p_wq_v, *p_wp_v;
    cudaGetSymbolAddress(&p_act_v, g_act);
    cudaGetSymbolAddress(&p_qkv_v, g_qkv);
    cudaGetSymbolAddress(&p_attb_v, g_attb);
    cudaGetSymbolAddress(&p_wq_v, g_wq);
    cudaGetSymbolAddress(&p_wp_v, g_wp);
    __nv_bfloat16* p_act  = (__nv_bfloat16*)p_act_v;
    __nv_bfloat16* p_qkv  = (__nv_bfloat16*)p_qkv_v;
    __nv_bfloat16* p_attb = (__nv_bfloat16*)p_attb_v;
    __nv_bfloat16* p_wq   = (__nv_bfloat16*)p_wq_v;
    __nv_bfloat16* p_wp   = (__nv_bfloat16*)p_wp_v;

    cudaFuncSetAttribute(tc_gemm, cudaFuncAttributeMaxDynamicSharedMemorySize, GSMEM_SZ);
    cudaFuncSetAttribute(tc_gemm_resid, cudaFuncAttributeMaxDynamicSharedMemorySize, GSMEM_SZ);
    cudaFuncSetAttribute(k1_ln, cudaFuncAttributeMaxDynamicSharedMemorySize, K1_SMEM);
    cudaFuncSetAttribute(k3_attn, cudaFuncAttributeMaxDynamicSharedMemorySize, K3_SMEM);

    wcvt<<<(3 * CC * CC + 255) / 256, 256>>>(qkv_w, proj_w, p_wq, p_wp);

    k1_ln<<<BB * TT * HH, 256, K1_SMEM>>>(x, ln_g, ln_b, p_act);

    {
        dim3 grid(3 * CC / 128, ROWS / 128);
        tc_gemm<<<grid, 256, GSMEM_SZ>>>(p_act, p_wq, qkv_b, p_qkv, ROWS, 3 * CC);
    }

    k3_attn<<<BSEQ, 256, K3_SMEM>>>(p_qkv, k_table, v_table, p_attb);

    {
        dim3 grid(CC / 128, ROWS / 128);
        tc_gemm_resid<<<grid, 256, GSMEM_SZ>>>(p_attb, p_wp, proj_b, x, out);
    }
}

// round 13
// speedup vs baseline: 1.1855x; 1.0143x over previous
#include <cuda_runtime.h>
#include <cuda_bf16.h>
#include <cstdint>

#define BB   2
#define CC   512
#define TT   16
#define HH   32
#define WW   32
#define NH   8
#define CH   64
#define BSEQ (BB*HH*WW)     // 2048
#define ROWS (BSEQ*TT)      // 32768
#define GK   512

// Row layout for all seq tensors: row = (b*16 + t)*1024 + h*32 + w
__device__ __nv_bfloat16 g_act[(size_t)ROWS * CC];
__device__ __nv_bfloat16 g_qkv[(size_t)ROWS * 3 * CC];
__device__ __nv_bfloat16 g_attb[(size_t)ROWS * CC];
__device__ __nv_bfloat16 g_wq[(size_t)3 * CC * CC];
__device__ __nv_bfloat16 g_wp[(size_t)CC * CC];

// ---------------------------------------------------------------------------
__device__ __forceinline__ uint32_t smem_u32(const void* p) {
    uint32_t a;
    asm("{ .reg .u64 t; cvta.to.shared.u64 t, %1; cvt.u32.u64 %0, t; }" : "=r"(a) : "l"(p));
    return a;
}
#define SWZ(o) ((o) ^ ((((uint32_t)(o)) >> 3) & 0x70))

__device__ __forceinline__ void cpasync16(uint32_t dst, const void* src) {
    asm volatile("cp.async.cg.shared.global [%0], [%1], 16;" :: "r"(dst), "l"(src));
}
__device__ __forceinline__ void ldsm_x4(uint32_t* r, uint32_t addr) {
    asm volatile("ldmatrix.sync.aligned.m8n8.x4.shared.b16 {%0,%1,%2,%3}, [%4];"
                 : "=r"(r[0]), "=r"(r[1]), "=r"(r[2]), "=r"(r[3]) : "r"(addr));
}
__device__ __forceinline__ void mma_bf16(float* c, const uint32_t* a, uint32_t b0, uint32_t b1) {
    asm volatile(
        "mma.sync.aligned.m16n8k16.row.col.f32.bf16.bf16.f32 "
        "{%0,%1,%2,%3}, {%4,%5,%6,%7}, {%8,%9}, {%0,%1,%2,%3};"
        : "+f"(c[0]), "+f"(c[1]), "+f"(c[2]), "+f"(c[3])
        : "r"(a[0]), "r"(a[1]), "r"(a[2]), "r"(a[3]), "r"(b0), "r"(b1));
}
__device__ __forceinline__ unsigned short bfbits(float x) {
    __nv_bfloat16 b = __float2bfloat16_rn(x);
    return *reinterpret_cast<unsigned short*>(&b);
}

// ---------------------------------------------------------------------------
__global__ __launch_bounds__(256) void wcvt(const float* __restrict__ qkv_w,
                                            const float* __restrict__ proj_w,
                                            __nv_bfloat16* __restrict__ wq,
                                            __nv_bfloat16* __restrict__ wp) {
    int i = blockIdx.x * 256 + threadIdx.x;
    if (i < 3 * CC * CC) wq[i] = __float2bfloat16_rn(qkv_w[i]);
    if (i < CC * CC)     wp[i] = __float2bfloat16_rn(proj_w[i]);
}

// ---------------------------------------------------------------------------
// BF16 GEMM-NT pieces (unchanged structure)
// ---------------------------------------------------------------------------
#define NSTAGE   3
#define STAGE_SZ 32768
#define GSMEM_SZ (NSTAGE*STAGE_SZ)
#define NCH      (GK >> 6)          // 8

__global__ __launch_bounds__(256, 2) void tc_gemm(const __nv_bfloat16* __restrict__ A,
                                                  const __nv_bfloat16* __restrict__ W,
                                                  const float* __restrict__ bias,
                                                  __nv_bfloat16* __restrict__ C,
                                                  int M, int N) {
    extern __shared__ __align__(1024) char smraw[];
    const uint32_t base = smem_u32(smraw);

    const int tid  = threadIdx.x;
    const int wid  = tid >> 5, lane = tid & 31;
    const int wm   = wid & 1, wn = wid >> 1;
    const int bn   = blockIdx.x, bm = blockIdx.y;

    uint32_t st_off[4];
    const __nv_bfloat16* ga[4];
    const __nv_bfloat16* gw[4];
    #pragma unroll
    for (int it = 0; it < 4; it++) {
        int idx = tid + it * 256;
        int r = idx >> 3, c16 = idx & 7;
        st_off[it] = SWZ((uint32_t)(r * 128 + c16 * 16));
        ga[it] = A + (size_t)(bm * 128 + r) * GK + c16 * 8;
        gw[it] = W + (size_t)(bn * 128 + r) * GK + c16 * 8;
    }

    auto load_chunk = [&](int l) {
        const int k0 = l << 6;
        const uint32_t sA = base + (l % NSTAGE) * STAGE_SZ;
        const uint32_t sB = sA + 16384;
        #pragma unroll
        for (int it = 0; it < 4; it++) {
            cpasync16(sA + st_off[it], ga[it] + k0);
            cpasync16(sB + st_off[it], gw[it] + k0);
        }
        asm volatile("cp.async.commit_group;" ::: "memory");
    };

    load_chunk(0);
    load_chunk(1);

    const int m_row_in = ((lane >> 3) & 1) * 8 + (lane & 7);
    const int m_kb     = (lane >> 4) * 16;
    uint32_t a_off[4], b_off[2];
    #pragma unroll
    for (int f = 0; f < 4; f++) {
        int row = wm * 64 + f * 16 + m_row_in;
        a_off[f] = (uint32_t)(row * 128 + (m_kb ^ ((row & 7) << 4)));
    }
    #pragma unroll
    for (int p = 0; p < 2; p++) {
        int row = wn * 32 + p * 16 + m_row_in;
        b_off[p] = (uint32_t)(row * 128 + (m_kb ^ ((row & 7) << 4)));
    }

    float acc[4][4][4];
    #pragma unroll
    for (int f = 0; f < 4; f++)
        #pragma unroll
        for (int g = 0; g < 4; g++)
            #pragma unroll
            for (int r = 0; r < 4; r++) acc[f][g][r] = 0.f;

    #pragma unroll
    for (int c = 0; c < NCH; c++) {
        asm volatile("cp.async.wait_group 1;" ::: "memory");
        __syncthreads();
        if (c + 2 < NCH) load_chunk(c + 2);

        const uint32_t sA = base + (c % NSTAGE) * STAGE_SZ;
        const uint32_t sB = sA + 16384;
        #pragma unroll
        for (int ks = 0; ks < 4; ks++) {
            uint32_t a[4][4], b[2][4];
            #pragma unroll
            for (int f = 0; f < 4; f++)
                ldsm_x4(a[f], sA + (a_off[f] ^ (ks << 5)));
            #pragma unroll
            for (int p = 0; p < 2; p++)
                ldsm_x4(b[p], sB + (b_off[p] ^ (ks << 5)));
            #pragma unroll
            for (int f = 0; f < 4; f++)
                #pragma unroll
                for (int g = 0; g < 4; g++)
                    mma_bf16(acc[f][g], a[f], b[g >> 1][g & 1], b[g >> 1][(g & 1) + 2]);
        }
        __syncthreads();
    }

    const int col_in = 2 * (lane & 3);
    #pragma unroll
    for (int g = 0; g < 4; g++) {
        const int col = bn * 128 + wn * 32 + g * 8 + col_in;
        const float b0 = bias[col], b1 = bias[col + 1];
        #pragma unroll
        for (int f = 0; f < 4; f++) {
            const size_t r0 = (size_t)bm * 128 + wm * 64 + f * 16 + (lane >> 2);
            __nv_bfloat162 p0, p1;
            p0.x = __float2bfloat16_rn(acc[f][g][0] + b0);
            p0.y = __float2bfloat16_rn(acc[f][g][1] + b1);
            p1.x = __float2bfloat16_rn(acc[f][g][2] + b0);
            p1.y = __float2bfloat16_rn(acc[f][g][3] + b1);
            *(__nv_bfloat162*)(C + r0 * N + col)       = p0;
            *(__nv_bfloat162*)(C + (r0 + 8) * N + col) = p1;
        }
    }
}

// Proj GEMM fused with residual + transpose-back (unchanged from round 12)
__global__ __launch_bounds__(256, 2) void tc_gemm_resid(const __nv_bfloat16* __restrict__ A,
                                                        const __nv_bfloat16* __restrict__ W,
                                                        const float* __restrict__ bias,
                                                        const float* __restrict__ x,
                                                        float* __restrict__ out) {
    extern __shared__ __align__(1024) char smraw[];
    const uint32_t base = smem_u32(smraw);

    const int tid  = threadIdx.x;
    const int wid  = tid >> 5, lane = tid & 31;
    const int wm   = wid & 1, wn = wid >> 1;
    const int bn   = blockIdx.x, bm = blockIdx.y;

    uint32_t st_off[4];
    const __nv_bfloat16* ga[4];
    const __nv_bfloat16* gw[4];
    #pragma unroll
    for (int it = 0; it < 4; it++) {
        int idx = tid + it * 256;
        int r = idx >> 3, c16 = idx & 7;
        st_off[it] = SWZ((uint32_t)(r * 128 + c16 * 16));
        ga[it] = A + (size_t)(bm * 128 + r) * GK + c16 * 8;
        gw[it] = W + (size_t)(bn * 128 + r) * GK + c16 * 8;
    }

    auto load_chunk = [&](int l) {
        const int k0 = l << 6;
        const uint32_t sA = base + (l % NSTAGE) * STAGE_SZ;
        const uint32_t sB = sA + 16384;
        #pragma unroll
        for (int it = 0; it < 4; it++) {
            cpasync16(sA + st_off[it], ga[it] + k0);
            cpasync16(sB + st_off[it], gw[it] + k0);
        }
        asm volatile("cp.async.commit_group;" ::: "memory");
    };

    load_chunk(0);
    load_chunk(1);

    const int m_row_in = ((lane >> 3) & 1) * 8 + (lane & 7);
    const int m_kb     = (lane >> 4) * 16;
    uint32_t a_off[4], b_off[2];
    #pragma unroll
    for (int f = 0; f < 4; f++) {
        int row = wm * 64 + f * 16 + m_row_in;
        a_off[f] = (uint32_t)(row * 128 + (m_kb ^ ((row & 7) << 4)));
    }
    #pragma unroll
    for (int p = 0; p < 2; p++) {
        int row = wn * 32 + p * 16 + m_row_in;
        b_off[p] = (uint32_t)(row * 128 + (m_kb ^ ((row & 7) << 4)));
    }

    float acc[4][4][4];
    #pragma unroll
    for (int f = 0; f < 4; f++)
        #pragma unroll
        for (int g = 0; g < 4; g++)
            #pragma unroll
            for (int r = 0; r < 4; r++) acc[f][g][r] = 0.f;

    #pragma unroll
    for (int c = 0; c < NCH; c++) {
        asm volatile("cp.async.wait_group 1;" ::: "memory");
        __syncthreads();
        if (c + 2 < NCH) load_chunk(c + 2);

        const uint32_t sA = base + (c % NSTAGE) * STAGE_SZ;
        const uint32_t sB = sA + 16384;
        #pragma unroll
        for (int ks = 0; ks < 4; ks++) {
            uint32_t a[4][4], b[2][4];
            #pragma unroll
            for (int f = 0; f < 4; f++)
                ldsm_x4(a[f], sA + (a_off[f] ^ (ks << 5)));
            #pragma unroll
            for (int p = 0; p < 2; p++)
                ldsm_x4(b[p], sB + (b_off[p] ^ (ks << 5)));
            #pragma unroll
            for (int f = 0; f < 4; f++)
                #pragma unroll
                for (int g = 0; g < 4; g++)
                    mma_bf16(acc[f][g], a[f], b[g >> 1][g & 1], b[g >> 1][(g & 1) + 2]);
        }
        __syncthreads();
    }

    float* T = (float*)smraw;
    const int col_in = 2 * (lane & 3);
    #pragma unroll
    for (int g = 0; g < 4; g++) {
        const int cl = wn * 32 + g * 8 + col_in;
        const float b0 = bias[bn * 128 + cl], b1 = bias[bn * 128 + cl + 1];
        #pragma unroll
        for (int f = 0; f < 4; f++) {
            const int m0 = wm * 64 + f * 16 + (lane >> 2);
            T[m0 * 129 + cl]           = acc[f][g][0] + b0;
            T[m0 * 129 + cl + 1]       = acc[f][g][1] + b1;
            T[(m0 + 8) * 129 + cl]     = acc[f][g][2] + b0;
            T[(m0 + 8) * 129 + cl + 1] = acc[f][g][3] + b1;
        }
    }
    __syncthreads();

    const int bb  = bm >> 7;
    const int rem = bm & 127;
    const int tt  = rem >> 3;
    const int hw0 = (rem & 7) * 128;
    const size_t obase = (size_t)bb * (CC * TT * HH * WW) + (size_t)tt * (HH * WW) + hw0;

    #pragma unroll
    for (int it = 0; it < 16; it++) {
        int q = tid + it * 256;
        int n = q >> 5;
        int m0 = q & 31;
        size_t gcol = obase + (size_t)(bn * 128 + n) * (TT * HH * WW) + m0;
        #pragma unroll
        for (int u = 0; u < 4; u++) {
            int m = m0 + u * 32;
            out[gcol + u * 32] = x[gcol + u * 32] + T[m * 129 + n];
        }
    }
}

// ---------------------------------------------------------------------------
// K1: LayerNorm -> bf16 g_act (unchanged from round 12)
// ---------------------------------------------------------------------------
#define K1_SMEM (512 * 33 * 4)

__global__ __launch_bounds__(256) void k1_ln(const float* __restrict__ x,
                                             const float* __restrict__ gamma,
                                             const float* __restrict__ beta,
                                             __nv_bfloat16* __restrict__ nrm) {
    extern __shared__ float tile[];
    int bid = blockIdx.x;
    int b = bid >> 9;
    int t = (bid >> 5) & 15;
    int h = bid & 31;
    int tid = threadIdx.x;
    int lane = tid & 31, r = tid >> 5;

    size_t xbase = (size_t)b * (CC * TT * HH * WW) + (size_t)t * (HH * WW) + (size_t)h * WW;

    #pragma unroll
    for (int it = 0; it < 16; it++) {
        int e = tid + it * 256;
        int cc = e >> 3, w4 = (e & 7) * 4;
        float4 v = *(const float4*)(x + xbase + (size_t)cc * (TT*HH*WW) + w4);
        tile[cc * 33 + w4 + 0] = v.x;
        tile[cc * 33 + w4 + 1] = v.y;
        tile[cc * 33 + w4 + 2] = v.z;
        tile[cc * 33 + w4 + 3] = v.w;
    }
    __syncthreads();

    float s = 0.f, s2 = 0.f;
    for (int cc = r; cc < CC; cc += 8) {
        float v = tile[cc * 33 + lane];
        s += v; s2 += v * v;
    }
    __shared__ float red0[8][32], red1[8][32];
    __shared__ float mu_s[32], rs_s[32];
    red0[r][lane] = s; red1[r][lane] = s2;
    __syncthreads();
    if (tid < 32) {
        float a = 0.f, q = 0.f;
        #pragma unroll
        for (int i = 0; i < 8; i++) { a += red0[i][tid]; q += red1[i][tid]; }
        float mu = a * (1.f / CC);
        float var = q * (1.f / CC) - mu * mu;
        mu_s[tid] = mu;
        rs_s[tid] = rsqrtf(var + 1e-5f);
    }
    __syncthreads();

    size_t obase = ((size_t)((b * 16 + t) * 1024 + h * 32)) * CC;

    #pragma unroll
    for (int it = 0; it < 32; it++) {
        int e = tid + it * 256;
        int ww = e >> 8, c2 = (e & 255) * 2;
        float mu = mu_s[ww], rs = rs_s[ww];
        float v0 = (tile[c2 * 33 + ww] - mu) * rs * __ldg(gamma + c2) + __ldg(beta + c2);
        float v1 = (tile[(c2 + 1) * 33 + ww] - mu) * rs * __ldg(gamma + c2 + 1) + __ldg(beta + c2 + 1);
        __nv_bfloat162 p;
        p.x = __float2bfloat16_rn(v0);
        p.y = __float2bfloat16_rn(v1);
        *(__nv_bfloat162*)(nrm + obase + (size_t)ww * CC + c2) = p;
    }
}

// ---------------------------------------------------------------------------
// K3: all-bf16 tensor-core attention (m16n8k16), fp32 accum/softmax.
// Smem word strides (bank-conflict-free scalar gathers):
//   Q: 52, K/ktab: 36, attn/V^T: 12, attn2/vtab^T: 20, S2raw(fp32): 33
// Per-warp regions: A = 832 words (Q -> S2raw -> V^T), B = 576 words (K -> attn+attn2)
// ---------------------------------------------------------------------------
#define K3_SMEM 54784
#define QROW ((size_t)1024 * 3 * CC)
#define OROW ((size_t)1024 * CC)

__global__ __launch_bounds__(256, 3) void k3_attn(const __nv_bfloat16* __restrict__ qkv,
                                                  const float* __restrict__ k_table,
                                                  const float* __restrict__ v_table,
                                                  __nv_bfloat16* __restrict__ aout) {
    extern __shared__ __align__(1024) uint32_t sm32[];
    const int tid = threadIdx.x;
    const int w = tid >> 5, lane = tid & 31;
    const int Bidx = blockIdx.x;
    const int b = Bidx >> 10, hw = Bidx & 1023;
    const int r = lane >> 2, qc = lane & 3;

    uint32_t* ktab  = sm32;                       // 32 x 36 words
    uint32_t* vtabT = sm32 + 1152;                // 64 x 20 words
    uint32_t* warpA = sm32 + 2432 + w * 1408;     // 832 words
    uint32_t* warpB = warpA + 832;                // 576 words
    float*    warpAf = (float*)warpA;

    // ---- stage tables (block-wide): ktab natural bf16, vtab transposed bf16
    {
        int d = tid >> 3, q4 = tid & 7;
        uint4 kw = make_uint4(0, 0, 0, 0);
        float vf[8];
        #pragma unroll
        for (int j = 0; j < 8; j++) vf[j] = 0.f;
        if (d < 31) {
            const float* kr = k_table + (size_t)(49 + d) * CH + q4 * 8;
            const float* vr = v_table + (size_t)(49 + d) * CH + q4 * 8;
            float4 f0 = *(const float4*)kr;
            float4 f1 = *(const float4*)(kr + 4);
            kw.x = (uint32_t)bfbits(f0.x) | ((uint32_t)bfbits(f0.y) << 16);
            kw.y = (uint32_t)bfbits(f0.z) | ((uint32_t)bfbits(f0.w) << 16);
            float4 g0 = *(const float4*)(kr + 0);
            (void)g0;
            float4 h0 = f1;
            kw.z = (uint32_t)bfbits(h0.x) | ((uint32_t)bfbits(h0.y) << 16);
            kw.w = (uint32_t)bfbits(h0.z) | ((uint32_t)bfbits(h0.w) << 16);
            float4 v0 = *(const float4*)vr;
            float4 v1 = *(const float4*)(vr + 4);
            vf[0] = v0.x; vf[1] = v0.y; vf[2] = v0.z; vf[3] = v0.w;
            vf[4] = v1.x; vf[5] = v1.y; vf[6] = v1.z; vf[7] = v1.w;
        }
        *(uint4*)(ktab + d * 36 + q4 * 4) = kw;
        unsigned short* vt16 = (unsigned short*)vtabT;
        #pragma unroll
        for (int j = 0; j < 8; j++) {
            int n = q4 * 8 + j;
            vt16[(n * 20 + (d >> 1)) * 2 + (d & 1)] = bfbits(vf[j]);
        }
    }

    // ---- stage Q, K (raw bf16 uint4 copies)
    const __nv_bfloat16* gq = qkv + ((size_t)b * 16384 + hw) * (3 * CC) + w * CH;
    #pragma unroll
    for (int it = 0; it < 4; it++) {
        int idx = lane + it * 32;
        int row = idx >> 3, q4 = idx & 7;
        uint4 vq = *(const uint4*)(gq + (size_t)row * QROW + q4 * 8);
        uint4 vk = *(const uint4*)(gq + (size_t)row * QROW + CC + q4 * 8);
        *(uint4*)(warpA + row * 52 + q4 * 4) = vq;
        *(uint4*)(warpB + row * 36 + q4 * 4) = vk;
    }
    __syncthreads();

    // ---- scores: S1 = Q@K^T (2 n-blocks over t), S2 = Q@ktab^T (4 n-blocks over d)
    float c1[2][4] = {{0.f,0.f,0.f,0.f},{0.f,0.f,0.f,0.f}};
    float c2[4][4] = {{0.f,0.f,0.f,0.f},{0.f,0.f,0.f,0.f},{0.f,0.f,0.f,0.f},{0.f,0.f,0.f,0.f}};
    #pragma unroll
    for (int ks = 0; ks < 4; ks++) {
        uint32_t a[4];
        a[0] = warpA[r * 52 + qc + 8 * ks];
        a[1] = warpA[(r + 8) * 52 + qc + 8 * ks];
        a[2] = warpA[r * 52 + qc + 4 + 8 * ks];
        a[3] = warpA[(r + 8) * 52 + qc + 4 + 8 * ks];
        #pragma unroll
        for (int nb = 0; nb < 2; nb++) {
            uint32_t b0 = warpB[(nb * 8 + r) * 36 + qc + 8 * ks];
            uint32_t b1 = warpB[(nb * 8 + r) * 36 + qc + 4 + 8 * ks];
            mma_bf16(c1[nb], a, b0, b1);
        }
        #pragma unroll
        for (int nb = 0; nb < 4; nb++) {
            uint32_t b0 = ktab[(nb * 8 + r) * 36 + qc + 8 * ks];
            uint32_t b1 = ktab[(nb * 8 + r) * 36 + qc + 4 + 8 * ks];
            mma_bf16(c2[nb], a, b0, b1);
        }
    }
    __syncwarp();

    // ---- S2raw fp32 [16][33] into region A (Q dead)
    #pragma unroll
    for (int nb = 0; nb < 4; nb++) {
        #pragma unroll
        for (int q = 0; q < 4; q++) {
            int row = r + (q >> 1) * 8;
            int col = nb * 8 + 2 * qc + (q & 1);
            warpAf[row * 33 + col] = c2[nb][q];
        }
    }
    // zero attn2 region (320 words at warpB+192; K dead)
    #pragma unroll
    for (int it = 0; it < 10; it++)
        warpB[192 + lane + it * 32] = 0;
    __syncwarp();

    // ---- combined scores + softmax
    float attv[2][4];
    #pragma unroll
    for (int h = 0; h < 2; h++) {
        int row = r + 8 * h;
        float v[4];
        #pragma unroll
        for (int m = 0; m < 4; m++) {
            int nb = m >> 1;
            int j = nb * 8 + 2 * qc + (m & 1);
            v[m] = (c1[nb][h * 2 + (m & 1)] + warpAf[row * 33 + (j - row + 15)]) * 0.125f;
        }
        float mx = fmaxf(fmaxf(v[0], v[1]), fmaxf(v[2], v[3]));
        mx = fmaxf(mx, __shfl_xor_sync(0xffffffffu, mx, 1));
        mx = fmaxf(mx, __shfl_xor_sync(0xffffffffu, mx, 2));
        float sum = 0.f;
        #pragma unroll
        for (int m = 0; m < 4; m++) { v[m] = __expf(v[m] - mx); sum += v[m]; }
        sum += __shfl_xor_sync(0xffffffffu, sum, 1);
        sum += __shfl_xor_sync(0xffffffffu, sum, 2);
        float inv = 1.f / sum;
        #pragma unroll
        for (int m = 0; m < 4; m++) attv[h][m] = v[m] * inv;
    }
    __syncwarp();

    // ---- write attn (bf16 pairs) + attn2 (skewed, halfword scatter) into region B
    {
        unsigned short* at2_16 = (unsigned short*)(warpB + 192);
        #pragma unroll
        for (int h = 0; h < 2; h++) {
            int row = r + 8 * h;
            uint32_t p0 = (uint32_t)bfbits(attv[h][0]) | ((uint32_t)bfbits(attv[h][1]) << 16);
            uint32_t p1 = (uint32_t)bfbits(attv[h][2]) | ((uint32_t)bfbits(attv[h][3]) << 16);
            warpB[row * 12 + qc]     = p0;
            warpB[row * 12 + 4 + qc] = p1;
            #pragma unroll
            for (int m = 0; m < 4; m++) {
                int j = (m >> 1) * 8 + 2 * qc + (m & 1);
                int col = j - row + 15;
                at2_16[(row * 20 + (col >> 1)) * 2 + (col & 1)] = bfbits(attv[h][m]);
            }
        }
    }

    // ---- stage V transposed into region A (S2raw dead)
    {
        unsigned short* At16 = (unsigned short*)warpA;
        #pragma unroll
        for (int it = 0; it < 4; it++) {
            int idx = lane + it * 32;
            int row = idx >> 3, q4 = idx & 7;
            uint4 vv = *(const uint4*)(gq + (size_t)row * QROW + 2 * CC + q4 * 8);
            unsigned short* u = (unsigned short*)&vv;
            #pragma unroll
            for (int j = 0; j < 8; j++) {
                int n = q4 * 8 + j;
                At16[(n * 12 + (row >> 1)) * 2 + (row & 1)] = u[j];
            }
        }
    }
    __syncwarp();

    // ---- output: O = attn@V + attn2@vtab
    uint32_t aat[4];
    aat[0] = warpB[r * 12 + qc];
    aat[1] = warpB[(r + 8) * 12 + qc];
    aat[2] = warpB[r * 12 + qc + 4];
    aat[3] = warpB[(r + 8) * 12 + qc + 4];
    uint32_t aa2[2][4];
    #pragma unroll
    for (int ks = 0; ks < 2; ks++) {
        aa2[ks][0] = warpB[192 + r * 20 + qc + 8 * ks];
        aa2[ks][1] = warpB[192 + (r + 8) * 20 + qc + 8 * ks];
        aa2[ks][2] = warpB[192 + r * 20 + qc + 4 + 8 * ks];
        aa2[ks][3] = warpB[192 + (r + 8) * 20 + qc + 4 + 8 * ks];
    }

    __nv_bfloat16* gaOut = aout + ((size_t)b * 16384 + hw) * CC + w * CH;
    #pragma unroll
    for (int nb = 0; nb < 8; nb++) {
        float o[4] = {0.f, 0.f, 0.f, 0.f};
        {
            uint32_t b0 = warpA[(nb * 8 + r) * 12 + qc];
            uint32_t b1 = warpA[(nb * 8 + r) * 12 + qc + 4];
            mma_bf16(o, aat, b0, b1);
        }
        #pragma unroll
        for (int ks = 0; ks < 2; ks++) {
            uint32_t b0 = vtabT[(nb * 8 + r) * 20 + qc + 8 * ks];
            uint32_t b1 = vtabT[(nb * 8 + r) * 20 + qc + 4 + 8 * ks];
            mma_bf16(o, aa2[ks], b0, b1);
        }
        int col = nb * 8 + 2 * qc;
        __nv_bfloat162 p0, p1;
        p0.x = __float2bfloat16_rn(o[0]); p0.y = __float2bfloat16_rn(o[1]);
        p1.x = __float2bfloat16_rn(o[2]); p1.y = __float2bfloat16_rn(o[3]);
        *(__nv_bfloat162*)(gaOut + (size_t)r * OROW + col)       = p0;
        *(__nv_bfloat162*)(gaOut + (size_t)(r + 8) * OROW + col) = p1;
    }
}

// ---------------------------------------------------------------------------
extern "C" void kernel_launch(void* const* d_in, const int* in_sizes, int n_in,
                              void* d_out, int out_size) {
    const float* x       = (const float*)d_in[0];
    const float* ln_g    = (const float*)d_in[1];
    const float* ln_b    = (const float*)d_in[2];
    const float* qkv_w   = (const float*)d_in[3];
    const float* qkv_b   = (const float*)d_in[4];
    const float* k_table = (const float*)d_in[5];
    const float* v_table = (const float*)d_in[6];
    const float* proj_w  = (const float*)d_in[7];
    const float* proj_b  = (const float*)d_in[8];
    float* out = (float*)d_out;

    void *p_act_v, *p_qkv_v, *p_attb_v, *p_wq_v, *p_wp_v;
    cudaGetSymbolAddress(&p_act_v, g_act);
    cudaGetSymbolAddress(&p_qkv_v, g_qkv);
    cudaGetSymbolAddress(&p_attb_v, g_attb);
    cudaGetSymbolAddress(&p_wq_v, g_wq);
    cudaGetSymbolAddress(&p_wp_v, g_wp);
    __nv_bfloat16* p_act  = (__nv_bfloat16*)p_act_v;
    __nv_bfloat16* p_qkv  = (__nv_bfloat16*)p_qkv_v;
    __nv_bfloat16* p_attb = (__nv_bfloat16*)p_attb_v;
    __nv_bfloat16* p_wq   = (__nv_bfloat16*)p_wq_v;
    __nv_bfloat16* p_wp   = (__nv_bfloat16*)p_wp_v;

    cudaFuncSetAttribute(tc_gemm, cudaFuncAttributeMaxDynamicSharedMemorySize, GSMEM_SZ);
    cudaFuncSetAttribute(tc_gemm_resid, cudaFuncAttributeMaxDynamicSharedMemorySize, GSMEM_SZ);
    cudaFuncSetAttribute(k1_ln, cudaFuncAttributeMaxDynamicSharedMemorySize, K1_SMEM);
    cudaFuncSetAttribute(k3_attn, cudaFuncAttributeMaxDynamicSharedMemorySize, K3_SMEM);

    wcvt<<<(3 * CC * CC + 255) / 256, 256>>>(qkv_w, proj_w, p_wq, p_wp);

    k1_ln<<<BB * TT * HH, 256, K1_SMEM>>>(x, ln_g, ln_b, p_act);

    {
        dim3 grid(3 * CC / 128, ROWS / 128);
        tc_gemm<<<grid, 256, GSMEM_SZ>>>(p_act, p_wq, qkv_b, p_qkv, ROWS, 3 * CC);
    }

    k3_attn<<<BSEQ, 256, K3_SMEM>>>(p_qkv, k_table, v_table, p_attb);

    {
        dim3 grid(CC / 128, ROWS / 128);
        tc_gemm_resid<<<grid, 256, GSMEM_SZ>>>(p_attb, p_wp, proj_b, x, out);
    }
}